// round 15
// baseline (speedup 1.0000x reference)
#include <cuda_runtime.h>
#include <cuda_fp16.h>
#include <math.h>
#include <stdint.h>

#define BB 4
#define SS 1024
#define DD 1024
#define HH 16
#define HD 64
#define BS (BB*SS)     /* 4096 */
#define DFF (4*DD)     /* 4096 */
#define QKVS 3072

// ---------------- scratch (static __device__, no allocations) ----------------
__device__ __half g_hh  [BS*DD];
__device__ __half g_qkvh[BS*QKVS];
__device__ __half g_ctxh[BS*DD];
__device__ float  g_x2  [BS*DD];
__device__ __half g_h2h [BS*DD];
__device__ __half g_midh[BS*DFF];
// k-major packed half2 weights: wqkv [3072][512], wo [1024][512], w1 [4096][512], w2 [1024][2048]
__device__ uint32_t g_wp[3072*512 + 1024*512 + 4096*512 + 1024*2048];

// ---------------- helpers ----------------
__device__ __forceinline__ void cpa16(void* d, const void* s) {
    asm volatile("cp.async.cg.shared.global [%0], [%1], 16;\n"
                 :: "r"((uint32_t)__cvta_generic_to_shared(d)), "l"(s));
}
__device__ __forceinline__ void cp_commit() { asm volatile("cp.async.commit_group;\n"); }
__device__ __forceinline__ void cp_wait0()  { asm volatile("cp.async.wait_group 0;\n"); }
__device__ __forceinline__ void cp_wait1()  { asm volatile("cp.async.wait_group 1;\n"); }

__device__ __forceinline__ uint32_t pack_h2(float x, float y) {
    __half2 h = __floats2half2_rn(x, y);
    return *(uint32_t*)&h;
}

__device__ __forceinline__ float gelu_f(float x) {
    float t = 0.7978845608028654f * (x + 0.044715f * x * x * x);
    return 0.5f * x * (1.0f + tanhf(t));
}

// fp16 m16n8k16 MMA, fp32 accumulate
__device__ __forceinline__ void mma_f16(float* c, uint32_t a0, uint32_t a1,
                                        uint32_t a2, uint32_t a3,
                                        uint32_t b0, uint32_t b1) {
    asm volatile(
        "mma.sync.aligned.m16n8k16.row.col.f32.f16.f16.f32 "
        "{%0,%1,%2,%3}, {%4,%5,%6,%7}, {%8,%9}, {%0,%1,%2,%3};"
        : "+f"(c[0]), "+f"(c[1]), "+f"(c[2]), "+f"(c[3])
        : "r"(a0), "r"(a1), "r"(a2), "r"(a3), "r"(b0), "r"(b1));
}

__device__ __forceinline__ void ldmx4(uint32_t& r0, uint32_t& r1,
                                      uint32_t& r2, uint32_t& r3, uint32_t addr) {
    asm volatile("ldmatrix.sync.aligned.m8n8.x4.shared.b16 {%0,%1,%2,%3}, [%4];"
                 : "=r"(r0), "=r"(r1), "=r"(r2), "=r"(r3) : "r"(addr));
}

__device__ __forceinline__ void ldmx4t(uint32_t& r0, uint32_t& r1,
                                       uint32_t& r2, uint32_t& r3, uint32_t addr) {
    asm volatile("ldmatrix.sync.aligned.m8n8.x4.trans.shared.b16 "
                 "{%0,%1,%2,%3}, [%4];"
                 : "=r"(r0), "=r"(r1), "=r"(r2), "=r"(r3) : "r"(addr));
}

// ---------------- weight pack-transpose: fp32 [K][N] -> u32 half2 [N][K/2] -----
// block (32,8); grid (N/32, K/64). tile[n][kc] in smem.
__global__ void pack_wT(const float* __restrict__ in, uint32_t* __restrict__ out,
                        int N, int K)
{
    __shared__ uint32_t tile[32][33];
    int n0 = blockIdx.x * 32;
    int k0 = blockIdx.y * 64;                 // 64 k rows = 32 kc
    int x = threadIdx.x, y = threadIdx.y;
    #pragma unroll
    for (int kcl = y; kcl < 32; kcl += 8)
        tile[x][kcl] = pack_h2(in[(size_t)(k0 + 2 * kcl) * N + n0 + x],
                               in[(size_t)(k0 + 2 * kcl + 1) * N + n0 + x]);
    __syncthreads();
    int Kh = K >> 1;
    #pragma unroll
    for (int nl = y; nl < 32; nl += 8)
        out[(size_t)(n0 + nl) * Kh + (k0 >> 1) + x] = tile[nl][x];
}

// ---------------- layernorm: fp32 in, fp16 out ----------------
__global__ void ln_kernel(const float* __restrict__ x,
                          const float* __restrict__ scale,
                          const float* __restrict__ shift,
                          __half* __restrict__ out)
{
    int row = blockIdx.x;
    int t = threadIdx.x;
    const float4 xv = ((const float4*)(x + (size_t)row * DD))[t];
    __shared__ float red[256];

    float s = xv.x + xv.y + xv.z + xv.w;
    red[t] = s; __syncthreads();
    for (int o = 128; o > 0; o >>= 1) { if (t < o) red[t] += red[t + o]; __syncthreads(); }
    float mean = red[0] * (1.0f / DD);
    __syncthreads();

    float d0 = xv.x - mean, d1 = xv.y - mean, d2 = xv.z - mean, d3 = xv.w - mean;
    red[t] = d0 * d0 + d1 * d1 + d2 * d2 + d3 * d3; __syncthreads();
    for (int o = 128; o > 0; o >>= 1) { if (t < o) red[t] += red[t + o]; __syncthreads(); }
    float rstd = rsqrtf(red[0] * (1.0f / DD) + 1e-5f);

    float4 sc = ((const float4*)scale)[t];
    float4 sh = ((const float4*)shift)[t];
    __half2* orow = (__half2*)(out + (size_t)row * DD);
    orow[t * 2]     = __floats2half2_rn(sc.x * d0 * rstd + sh.x, sc.y * d1 * rstd + sh.y);
    orow[t * 2 + 1] = __floats2half2_rn(sc.z * d2 * rstd + sh.z, sc.w * d3 * rstd + sh.w);
}

// ---------------- fp16 GEMM v10: ldmatrix frags, both operands k-major --------
// C[M,N] = A[M,K](fp16 row-major) @ Bp([N][K/2] u32 k-pair rows)
// 128 thr, 128x128 CTA, 64x64 warps, k16 stages, 3-stage cp.async.
#define ROWW 12
#define STG (2*128*ROWW)
#define GSMEM (3*STG*4)

__global__ __launch_bounds__(128)
void gemm_f16(const __half* __restrict__ A, const uint32_t* __restrict__ Bp,
              void* __restrict__ Cv, int M, int N, int K,
              const float* __restrict__ bias,
              const float* __restrict__ res,
              int gelu, int half_out)
{
    extern __shared__ uint32_t smh[];
    const int tid  = threadIdx.x;
    const int lane = tid & 31;
    const int warp = tid >> 5;           // 0..3
    const int g    = lane >> 2;
    const int tig  = lane & 3;
    const int mw   = (warp >> 1) * 64;   // 0 or 64
    const int nw   = (warp & 1) * 64;    // 0 or 64
    const int bx = blockIdx.x, by = blockIdx.y;
    const int Kh = K >> 1;

    const __half* Ab = A + (size_t)(by * 128) * K;
    const uint32_t* Bb = Bp + (size_t)(bx * 128) * Kh;

    float acc[4][8][4];
    #pragma unroll
    for (int i = 0; i < 4; i++)
        #pragma unroll
        for (int j = 0; j < 8; j++)
            #pragma unroll
            for (int c = 0; c < 4; c++) acc[i][j][c] = 0.f;

    const int T = K / 16;
    const int lrow = lane & 15;          // ldmatrix row-provider index
    const int lchk = (lane >> 4) * 4;    // ldmatrix 16B chunk (in u32)

#define ISSUE(sidx, k0) do {                                                     \
        uint32_t* As_ = smh + (sidx) * STG;                                      \
        uint32_t* Bs_ = As_ + 128 * ROWW;                                        \
        cpa16(&As_[tid * ROWW],     Ab + (size_t)tid * K + (k0));                \
        cpa16(&As_[tid * ROWW + 4], Ab + (size_t)tid * K + (k0) + 8);            \
        cpa16(&Bs_[tid * ROWW],     Bb + (size_t)tid * Kh + ((k0) >> 1));        \
        cpa16(&Bs_[tid * ROWW + 4], Bb + (size_t)tid * Kh + ((k0) >> 1) + 4);    \
        cp_commit();                                                             \
    } while (0)

    ISSUE(0, 0);
    ISSUE(1, 16);

    int st = 0;
    for (int t = 0; t < T; t++) {
        if (t + 2 < T) cp_wait1(); else cp_wait0();
        __syncthreads();
        if (t + 2 < T) {
            int sn = st + 2; if (sn >= 3) sn -= 3;
            ISSUE(sn, (t + 2) * 16);
        }
        const uint32_t* As = smh + st * STG;
        const uint32_t* Bs = As + 128 * ROWW;
        {
            uint32_t a[4][4], b[8][2];
            #pragma unroll
            for (int i = 0; i < 4; i++)
                ldmx4(a[i][0], a[i][1], a[i][2], a[i][3],
                      (uint32_t)__cvta_generic_to_shared(
                          &As[(mw + i * 16 + lrow) * ROWW + lchk]));
            #pragma unroll
            for (int j2 = 0; j2 < 4; j2++)
                ldmx4(b[2 * j2][0], b[2 * j2 + 1][0], b[2 * j2][1], b[2 * j2 + 1][1],
                      (uint32_t)__cvta_generic_to_shared(
                          &Bs[(nw + j2 * 16 + lrow) * ROWW + lchk]));
            #pragma unroll
            for (int i = 0; i < 4; i++)
                #pragma unroll
                for (int j = 0; j < 8; j++)
                    mma_f16(acc[i][j], a[i][0], a[i][1], a[i][2], a[i][3],
                            b[j][0], b[j][1]);
        }
        st++; if (st >= 3) st -= 3;
    }
#undef ISSUE

    #pragma unroll
    for (int i = 0; i < 4; i++) {
        int row = by * 128 + mw + i * 16 + g;
        #pragma unroll
        for (int j = 0; j < 8; j++) {
            int col = bx * 128 + nw + j * 8 + tig * 2;
            float v0 = acc[i][j][0], v1 = acc[i][j][1];
            float v2 = acc[i][j][2], v3 = acc[i][j][3];
            if (bias) {
                float b0 = bias[col], b1 = bias[col + 1];
                v0 += b0; v1 += b1; v2 += b0; v3 += b1;
            }
            if (gelu) { v0 = gelu_f(v0); v1 = gelu_f(v1); v2 = gelu_f(v2); v3 = gelu_f(v3); }
            size_t o0 = (size_t)row * N + col;
            size_t o1 = (size_t)(row + 8) * N + col;
            if (res) {
                v0 += res[o0]; v1 += res[o0 + 1];
                v2 += res[o1]; v3 += res[o1 + 1];
            }
            if (half_out) {
                __half* Ch = (__half*)Cv;
                *(__half2*)&Ch[o0] = __floats2half2_rn(v0, v1);
                *(__half2*)&Ch[o1] = __floats2half2_rn(v2, v3);
            } else {
                float* C = (float*)Cv;
                C[o0] = v0; C[o0 + 1] = v1;
                C[o1] = v2; C[o1 + 1] = v3;
            }
        }
    }
}

// ---------------- fused flash attention v3: full fp16 MMA ----------------
#define QW 36
#define FLASH_SMEM ((128*QW + 2*64*QW + 2*64*QW + 2*64) * 4)

__global__ __launch_bounds__(256, 2)
void flash_kernel(const __half* __restrict__ qkv, const int* __restrict__ amask,
                  __half* __restrict__ ctx)
{
    extern __shared__ uint32_t fsm[];
    uint32_t* Qs = fsm;                      // [128][36]
    uint32_t* Ks = Qs + 128 * QW;            // [2][64][36]
    uint32_t* Vs = Ks + 2 * 64 * QW;         // [2][64][36]
    float* mk = (float*)(Vs + 2 * 64 * QW);  // [2][64]

    const int tid = threadIdx.x, w = tid >> 5, lane = tid & 31;
    const int g = lane >> 2, tig = lane & 3;
    const int bh = blockIdx.y, b = bh >> 4, h = bh & 15;
    const int row0 = (gridDim.x - 1 - blockIdx.x) * 128;   // heavy tiles first
    const int ntiles = row0 / 64 + 2;

    const __half* qb = qkv + (size_t)(b * SS + row0) * QKVS + h * 64;
    const __half* kb = qkv + (size_t)(b * SS) * QKVS + 1024 + h * 64;
    const __half* vb = qkv + (size_t)(b * SS) * QKVS + 2048 + h * 64;

    #pragma unroll
    for (int i = 0; i < 4; i++) {
        int c = tid + i * 256; int r = c >> 3, ch = c & 7;
        cpa16(&Qs[r * QW + ch * 4], qb + (size_t)r * QKVS + ch * 8);
    }
    #pragma unroll
    for (int i = 0; i < 2; i++) {
        int c = tid + i * 256; int r = c >> 3, ch = c & 7;
        cpa16(&Ks[r * QW + ch * 4], kb + (size_t)r * QKVS + ch * 8);
        cpa16(&Vs[r * QW + ch * 4], vb + (size_t)r * QKVS + ch * 8);
    }
    if (tid < 64) mk[tid] = amask[b * SS + tid] ? 0.f : -1e30f;
    cp_commit();

    float m0 = -1e30f, m1 = -1e30f, l0s = 0.f, l1s = 0.f;
    float acc_o[8][4];
    #pragma unroll
    for (int nt = 0; nt < 8; nt++)
        #pragma unroll
        for (int c = 0; c < 4; c++) acc_o[nt][c] = 0.f;

    const int mrow = w * 16 + g;
    const int grow0 = row0 + mrow, grow1 = grow0 + 8;
    const int vrow_off = (lane & 15) * QW + ((lane & 16) >> 2);

    for (int t = 0; t < ntiles; t++) {
        const int st = t & 1;
        cp_wait0();
        __syncthreads();
        if (t + 1 < ntiles) {
            int j0n = (t + 1) * 64, sn = st ^ 1;
            const __half* kn = kb + (size_t)j0n * QKVS;
            const __half* vn = vb + (size_t)j0n * QKVS;
            #pragma unroll
            for (int i = 0; i < 2; i++) {
                int c = tid + i * 256; int r = c >> 3, ch = c & 7;
                cpa16(&Ks[(sn * 64 + r) * QW + ch * 4], kn + (size_t)r * QKVS + ch * 8);
                cpa16(&Vs[(sn * 64 + r) * QW + ch * 4], vn + (size_t)r * QKVS + ch * 8);
            }
            if (tid < 64) mk[sn * 64 + tid] = amask[b * SS + j0n + tid] ? 0.f : -1e30f;
            cp_commit();
        }
        const int j0 = t * 64;
        const uint32_t* Ksb = Ks + st * 64 * QW;
        const uint32_t* Vsb = Vs + st * 64 * QW;
        const float* mkb = mk + st * 64;

        // ---- S = Q K^T ----
        float accs[8][4];
        #pragma unroll
        for (int nt = 0; nt < 8; nt++)
            #pragma unroll
            for (int c = 0; c < 4; c++) accs[nt][c] = 0.f;
        #pragma unroll
        for (int ks = 0; ks < 4; ks++) {
            uint32_t a0 = Qs[mrow * QW + ks * 8 + tig];
            uint32_t a1 = Qs[(mrow + 8) * QW + ks * 8 + tig];
            uint32_t a2 = Qs[mrow * QW + ks * 8 + tig + 4];
            uint32_t a3 = Qs[(mrow + 8) * QW + ks * 8 + tig + 4];
            #pragma unroll
            for (int nt = 0; nt < 8; nt++) {
                int n = g + nt * 8;
                uint32_t b0 = Ksb[n * QW + ks * 8 + tig];
                uint32_t b1 = Ksb[n * QW + ks * 8 + tig + 4];
                mma_f16(accs[nt], a0, a1, a2, a3, b0, b1);
            }
        }

        // ---- mask + scale + rowmax ----
        float rm0 = -1e30f, rm1 = -1e30f;
        #pragma unroll
        for (int nt = 0; nt < 8; nt++) {
            int c0 = j0 + nt * 8 + tig * 2;
            float ma = mkb[nt * 8 + tig * 2], mb = mkb[nt * 8 + tig * 2 + 1];
            float s0 = accs[nt][0] * 0.125f + ma;
            float s1 = accs[nt][1] * 0.125f + mb;
            float s2 = accs[nt][2] * 0.125f + ma;
            float s3 = accs[nt][3] * 0.125f + mb;
            if (c0 > grow0)     s0 = -1e30f;
            if (c0 + 1 > grow0) s1 = -1e30f;
            if (c0 > grow1)     s2 = -1e30f;
            if (c0 + 1 > grow1) s3 = -1e30f;
            accs[nt][0] = s0; accs[nt][1] = s1; accs[nt][2] = s2; accs[nt][3] = s3;
            rm0 = fmaxf(rm0, fmaxf(s0, s1));
            rm1 = fmaxf(rm1, fmaxf(s2, s3));
        }
        rm0 = fmaxf(rm0, __shfl_xor_sync(0xffffffffu, rm0, 1));
        rm0 = fmaxf(rm0, __shfl_xor_sync(0xffffffffu, rm0, 2));
        rm1 = fmaxf(rm1, __shfl_xor_sync(0xffffffffu, rm1, 1));
        rm1 = fmaxf(rm1, __shfl_xor_sync(0xffffffffu, rm1, 2));

        float mn0 = fmaxf(m0, rm0), mn1 = fmaxf(m1, rm1);
        float corr0 = __expf(m0 - mn0), corr1 = __expf(m1 - mn1);
        m0 = mn0; m1 = mn1;

        // ---- P = exp(S - m), row sums ----
        float sum0 = 0.f, sum1 = 0.f;
        #pragma unroll
        for (int nt = 0; nt < 8; nt++) {
            float p0 = __expf(accs[nt][0] - m0);
            float p1 = __expf(accs[nt][1] - m0);
            float p2 = __expf(accs[nt][2] - m1);
            float p3 = __expf(accs[nt][3] - m1);
            sum0 += p0 + p1; sum1 += p2 + p3;
            accs[nt][0] = p0; accs[nt][1] = p1; accs[nt][2] = p2; accs[nt][3] = p3;
        }
        sum0 += __shfl_xor_sync(0xffffffffu, sum0, 1);
        sum0 += __shfl_xor_sync(0xffffffffu, sum0, 2);
        sum1 += __shfl_xor_sync(0xffffffffu, sum1, 1);
        sum1 += __shfl_xor_sync(0xffffffffu, sum1, 2);
        l0s = l0s * corr0 + sum0;
        l1s = l1s * corr1 + sum1;
        #pragma unroll
        for (int nt = 0; nt < 8; nt++) {
            acc_o[nt][0] *= corr0; acc_o[nt][1] *= corr0;
            acc_o[nt][2] *= corr1; acc_o[nt][3] *= corr1;
        }

        // ---- O += P V ----
        #pragma unroll
        for (int ks = 0; ks < 4; ks++) {
            uint32_t a0 = pack_h2(accs[2 * ks][0],     accs[2 * ks][1]);
            uint32_t a1 = pack_h2(accs[2 * ks][2],     accs[2 * ks][3]);
            uint32_t a2 = pack_h2(accs[2 * ks + 1][0], accs[2 * ks + 1][1]);
            uint32_t a3 = pack_h2(accs[2 * ks + 1][2], accs[2 * ks + 1][3]);
            const uint32_t* vrow = Vsb + ks * 16 * QW + vrow_off;
            #pragma unroll
            for (int n0 = 0; n0 < 4; n0++) {
                uint32_t r0, r1, r2, r3;
                ldmx4t(r0, r1, r2, r3,
                       (uint32_t)__cvta_generic_to_shared(vrow + n0 * 8));
                mma_f16(acc_o[n0 * 2],     a0, a1, a2, a3, r0, r1);
                mma_f16(acc_o[n0 * 2 + 1], a0, a1, a2, a3, r2, r3);
            }
        }
    }

    float i0 = 1.f / l0s, i1 = 1.f / l1s;
    size_t base0 = (size_t)(b * SS + grow0) * DD + h * 64;
    size_t base1 = (size_t)(b * SS + grow1) * DD + h * 64;
    #pragma unroll
    for (int nt = 0; nt < 8; nt++) {
        int col = nt * 8 + tig * 2;
        *(__half2*)&ctx[base0 + col] = __floats2half2_rn(acc_o[nt][0] * i0,
                                                         acc_o[nt][1] * i0);
        *(__half2*)&ctx[base1 + col] = __floats2half2_rn(acc_o[nt][2] * i1,
                                                         acc_o[nt][3] * i1);
    }
}

// ---------------- host launch ----------------
extern "C" void kernel_launch(void* const* d_in, const int* in_sizes, int n_in,
                              void* d_out, int out_size)
{
    const float* x     = (const float*)d_in[0];
    const int*   amask = (const int*)  d_in[1];
    const float* wq    = (const float*)d_in[2];
    const float* wk    = (const float*)d_in[3];
    const float* wv    = (const float*)d_in[4];
    const float* wo    = (const float*)d_in[5];
    const float* bo    = (const float*)d_in[6];
    const float* ln1s  = (const float*)d_in[7];
    const float* ln1b  = (const float*)d_in[8];
    const float* ln2s  = (const float*)d_in[9];
    const float* ln2b  = (const float*)d_in[10];
    const float* w1    = (const float*)d_in[11];
    const float* b1    = (const float*)d_in[12];
    const float* w2    = (const float*)d_in[13];
    const float* b2    = (const float*)d_in[14];
    float* out = (float*)d_out;

    __half *hh, *qkvh, *ctxh, *h2h, *midh;
    float *x2;
    uint32_t* wp;
    cudaGetSymbolAddress((void**)&hh,   g_hh);
    cudaGetSymbolAddress((void**)&qkvh, g_qkvh);
    cudaGetSymbolAddress((void**)&ctxh, g_ctxh);
    cudaGetSymbolAddress((void**)&x2,   g_x2);
    cudaGetSymbolAddress((void**)&h2h,  g_h2h);
    cudaGetSymbolAddress((void**)&midh, g_midh);
    cudaGetSymbolAddress((void**)&wp,   g_wp);

    uint32_t* wqkvP = wp;                                   // [3072][512]
    uint32_t* woP   = wp + 3072 * 512;                      // [1024][512]
    uint32_t* w1P   = woP + 1024 * 512;                     // [4096][512]
    uint32_t* w2P   = w1P + 4096 * 512;                     // [1024][2048]

    cudaFuncSetAttribute(flash_kernel,
                         cudaFuncAttributeMaxDynamicSharedMemorySize, FLASH_SMEM);
    cudaFuncSetAttribute(gemm_f16,
                         cudaFuncAttributeMaxDynamicSharedMemorySize, GSMEM);

    // weight pack-transpose to k-major [N][K/2]
    dim3 pb(32, 8);
    pack_wT<<<dim3(32, 16), pb>>>(wq, wqkvP,                1024, 1024);
    pack_wT<<<dim3(32, 16), pb>>>(wk, wqkvP + 1024 * 512,   1024, 1024);
    pack_wT<<<dim3(32, 16), pb>>>(wv, wqkvP + 2048 * 512,   1024, 1024);
    pack_wT<<<dim3(32, 16), pb>>>(wo, woP,                  1024, 1024);
    pack_wT<<<dim3(128, 16), pb>>>(w1, w1P,                 4096, 1024);
    pack_wT<<<dim3(32, 64), pb>>>(w2, w2P,                  1024, 4096);

    // LN1 (fp16 output)
    ln_kernel<<<BS, 256>>>(x, ln1s, ln1b, hh);

    // fused QKV projection -> fp16 qkv
    gemm_f16<<<dim3(QKVS / 128, BS / 128), 128, GSMEM>>>(
        hh, wqkvP, qkvh, BS, QKVS, DD, nullptr, nullptr, 0, 1);

    // fused attention (full fp16) -> fp16 ctx
    flash_kernel<<<dim3(SS / 128, BB * HH), 256, FLASH_SMEM>>>(qkvh, amask, ctxh);

    // output projection + residual -> fp32 x2
    gemm_f16<<<dim3(DD / 128, BS / 128), 128, GSMEM>>>(
        ctxh, woP, x2, BS, DD, DD, bo, x, 0, 0);

    // LN2 + FFN
    ln_kernel<<<BS, 256>>>(x2, ln2s, ln2b, h2h);
    gemm_f16<<<dim3(DFF / 128, BS / 128), 128, GSMEM>>>(
        h2h, w1P, midh, BS, DFF, DD, b1, nullptr, 1, 1);
    gemm_f16<<<dim3(DD / 128, BS / 128), 128, GSMEM>>>(
        midh, w2P, out, BS, DD, DFF, b2, x2, 0, 0);
}

// round 16
// speedup vs baseline: 1.2203x; 1.2203x over previous
#include <cuda_runtime.h>
#include <cuda_fp16.h>
#include <math.h>
#include <stdint.h>

#define BB 4
#define SS 1024
#define DD 1024
#define HH 16
#define HD 64
#define BS (BB*SS)     /* 4096 */
#define DFF (4*DD)     /* 4096 */
#define QKVS 3072

// ---------------- scratch (static __device__, no allocations) ----------------
__device__ __half g_hh  [BS*DD];
__device__ __half g_qkvh[BS*QKVS];
__device__ __half g_ctxh[BS*DD];
__device__ float  g_x2  [BS*DD];
__device__ __half g_h2h [BS*DD];
__device__ __half g_midh[BS*DFF];
// packed half2 weights: wqkv [512][3072], wo [512][1024], w1 [512][4096], w2 [2048][1024]
__device__ uint32_t g_wp[512*3072 + 512*1024 + 512*4096 + 2048*1024];

// ---------------- helpers ----------------
__device__ __forceinline__ void cpa16(void* d, const void* s) {
    asm volatile("cp.async.cg.shared.global [%0], [%1], 16;\n"
                 :: "r"((uint32_t)__cvta_generic_to_shared(d)), "l"(s));
}
__device__ __forceinline__ void cp_commit() { asm volatile("cp.async.commit_group;\n"); }
__device__ __forceinline__ void cp_wait0()  { asm volatile("cp.async.wait_group 0;\n"); }
__device__ __forceinline__ void cp_wait1()  { asm volatile("cp.async.wait_group 1;\n"); }

__device__ __forceinline__ uint32_t pack_h2(float x, float y) {
    __half2 h = __floats2half2_rn(x, y);
    return *(uint32_t*)&h;
}

__device__ __forceinline__ float gelu_f(float x) {
    float t = 0.7978845608028654f * (x + 0.044715f * x * x * x);
    return 0.5f * x * (1.0f + tanhf(t));
}

// fp16 m16n8k16 MMA, fp32 accumulate
__device__ __forceinline__ void mma_f16(float* c, uint32_t a0, uint32_t a1,
                                        uint32_t a2, uint32_t a3,
                                        uint32_t b0, uint32_t b1) {
    asm volatile(
        "mma.sync.aligned.m16n8k16.row.col.f32.f16.f16.f32 "
        "{%0,%1,%2,%3}, {%4,%5,%6,%7}, {%8,%9}, {%0,%1,%2,%3};"
        : "+f"(c[0]), "+f"(c[1]), "+f"(c[2]), "+f"(c[3])
        : "r"(a0), "r"(a1), "r"(a2), "r"(a3), "r"(b0), "r"(b1));
}

__device__ __forceinline__ void ldmx4(uint32_t& r0, uint32_t& r1,
                                      uint32_t& r2, uint32_t& r3, uint32_t addr) {
    asm volatile("ldmatrix.sync.aligned.m8n8.x4.shared.b16 {%0,%1,%2,%3}, [%4];"
                 : "=r"(r0), "=r"(r1), "=r"(r2), "=r"(r3) : "r"(addr));
}

__device__ __forceinline__ void ldmx4t(uint32_t& r0, uint32_t& r1,
                                       uint32_t& r2, uint32_t& r3, uint32_t addr) {
    asm volatile("ldmatrix.sync.aligned.m8n8.x4.trans.shared.b16 "
                 "{%0,%1,%2,%3}, [%4];"
                 : "=r"(r0), "=r"(r1), "=r"(r2), "=r"(r3) : "r"(addr));
}

// ---------------- weight packing: fp32 [K][N] -> half2 u32 [K/2][N] ----------------
__global__ void pack_qkvh(const float* __restrict__ wq, const float* __restrict__ wk,
                          const float* __restrict__ wv, uint32_t* __restrict__ out)
{
    int idx = blockIdx.x * 256 + threadIdx.x;   // over 512*1024
    int kc = idx >> 10, n = idx & 1023;
    size_t i0 = (size_t)(2 * kc) * 1024 + n;
    size_t i1 = i0 + 1024;
    size_t o = (size_t)kc * QKVS + n;
    out[o]        = pack_h2(wq[i0], wq[i1]);
    out[o + 1024] = pack_h2(wk[i0], wk[i1]);
    out[o + 2048] = pack_h2(wv[i0], wv[i1]);
}

__global__ void pack_wh(const float* __restrict__ in, uint32_t* __restrict__ out, int N)
{
    int idx = blockIdx.x * 256 + threadIdx.x;   // over (K/2)*N
    int kc = idx / N, n = idx - kc * N;
    size_t i0 = (size_t)(2 * kc) * N + n;
    out[idx] = pack_h2(in[i0], in[i0 + N]);
}

// ---------------- layernorm: fp32 in, fp16 out ----------------
__global__ void ln_kernel(const float* __restrict__ x,
                          const float* __restrict__ scale,
                          const float* __restrict__ shift,
                          __half* __restrict__ out)
{
    int row = blockIdx.x;
    int t = threadIdx.x;
    const float4 xv = ((const float4*)(x + (size_t)row * DD))[t];
    __shared__ float red[256];

    float s = xv.x + xv.y + xv.z + xv.w;
    red[t] = s; __syncthreads();
    for (int o = 128; o > 0; o >>= 1) { if (t < o) red[t] += red[t + o]; __syncthreads(); }
    float mean = red[0] * (1.0f / DD);
    __syncthreads();

    float d0 = xv.x - mean, d1 = xv.y - mean, d2 = xv.z - mean, d3 = xv.w - mean;
    red[t] = d0 * d0 + d1 * d1 + d2 * d2 + d3 * d3; __syncthreads();
    for (int o = 128; o > 0; o >>= 1) { if (t < o) red[t] += red[t + o]; __syncthreads(); }
    float rstd = rsqrtf(red[0] * (1.0f / DD) + 1e-5f);

    float4 sc = ((const float4*)scale)[t];
    float4 sh = ((const float4*)shift)[t];
    __half2* orow = (__half2*)(out + (size_t)row * DD);
    orow[t * 2]     = __floats2half2_rn(sc.x * d0 * rstd + sh.x, sc.y * d1 * rstd + sh.y);
    orow[t * 2 + 1] = __floats2half2_rn(sc.z * d2 * rstd + sh.z, sc.w * d3 * rstd + sh.w);
}

// ---------------- fp16 GEMM v11: R14 + ldmatrix A-frags --------
// C[M,N] = A[M,K](fp16 row-major) @ Bp(half2-packed [K/2][N])
// 128 thr, 128x128 CTA, 64x64 warps, k16 stages, 3-stage cp.async.
#define ASZ (128*12)
#define BSZ (8*136)
#define STG (ASZ+BSZ)
#define GSMEM (3*STG*4)

__global__ __launch_bounds__(128)
void gemm_f16(const __half* __restrict__ A, const uint32_t* __restrict__ Bp,
              void* __restrict__ Cv, int M, int N, int K,
              const float* __restrict__ bias,
              const float* __restrict__ res,
              int gelu, int half_out)
{
    extern __shared__ uint32_t smh[];
    const int tid  = threadIdx.x;
    const int lane = tid & 31;
    const int warp = tid >> 5;           // 0..3
    const int g    = lane >> 2;
    const int tig  = lane & 3;
    const int mw   = (warp >> 1) * 64;   // 0 or 64
    const int nw   = (warp & 1) * 64;    // 0 or 64
    const int bx = blockIdx.x, by = blockIdx.y;

    const __half* Ab = A + (size_t)(by * 128) * K;
    const uint32_t* Bb = Bp + bx * 128;

    float acc[4][8][4];
    #pragma unroll
    for (int i = 0; i < 4; i++)
        #pragma unroll
        for (int j = 0; j < 8; j++)
            #pragma unroll
            for (int c = 0; c < 4; c++) acc[i][j][c] = 0.f;

    const int T = K / 16;
    const int ar = tid >> 1, ak = tid & 1;
    const int br = tid >> 5, bn = (tid & 31) * 4;
    const int lrow = lane & 15;          // ldmatrix row-provider
    const int lchk = (lane >> 4) * 4;    // ldmatrix 16B chunk (u32)

#define ISSUE(sidx, k0) do {                                                     \
        uint32_t* As_ = smh + (sidx) * STG;                                      \
        uint32_t* Bs_ = As_ + ASZ;                                               \
        cpa16(&As_[ar * 12 + ak * 4],        Ab + (size_t)ar * K + (k0) + ak * 8); \
        cpa16(&As_[(ar + 64) * 12 + ak * 4], Ab + (size_t)(ar + 64) * K + (k0) + ak * 8); \
        cpa16(&Bs_[br * 136 + bn],       Bb + (size_t)(((k0) >> 1) + br) * N + bn); \
        cpa16(&Bs_[(br + 4) * 136 + bn], Bb + (size_t)(((k0) >> 1) + br + 4) * N + bn); \
        cp_commit();                                                             \
    } while (0)

    ISSUE(0, 0);
    ISSUE(1, 16);

    int st = 0;
    for (int t = 0; t < T; t++) {
        if (t + 2 < T) cp_wait1(); else cp_wait0();
        __syncthreads();
        if (t + 2 < T) {
            int sn = st + 2; if (sn >= 3) sn -= 3;
            ISSUE(sn, (t + 2) * 16);
        }
        const uint32_t* As = smh + st * STG;
        const uint32_t* Bs = As + ASZ;
        {
            uint32_t a[4][4], b[8][2];
            #pragma unroll
            for (int i = 0; i < 4; i++)
                ldmx4(a[i][0], a[i][1], a[i][2], a[i][3],
                      (uint32_t)__cvta_generic_to_shared(
                          &As[(mw + i * 16 + lrow) * 12 + lchk]));
            #pragma unroll
            for (int j = 0; j < 8; j++) {
                int n = nw + j * 8 + g;
                b[j][0] = Bs[tig * 136 + n];
                b[j][1] = Bs[(tig + 4) * 136 + n];
            }
            #pragma unroll
            for (int i = 0; i < 4; i++)
                #pragma unroll
                for (int j = 0; j < 8; j++)
                    mma_f16(acc[i][j], a[i][0], a[i][1], a[i][2], a[i][3],
                            b[j][0], b[j][1]);
        }
        st++; if (st >= 3) st -= 3;
    }
#undef ISSUE

    #pragma unroll
    for (int i = 0; i < 4; i++) {
        int row = by * 128 + mw + i * 16 + g;
        #pragma unroll
        for (int j = 0; j < 8; j++) {
            int col = bx * 128 + nw + j * 8 + tig * 2;
            float v0 = acc[i][j][0], v1 = acc[i][j][1];
            float v2 = acc[i][j][2], v3 = acc[i][j][3];
            if (bias) {
                float b0 = bias[col], b1 = bias[col + 1];
                v0 += b0; v1 += b1; v2 += b0; v3 += b1;
            }
            if (gelu) { v0 = gelu_f(v0); v1 = gelu_f(v1); v2 = gelu_f(v2); v3 = gelu_f(v3); }
            size_t o0 = (size_t)row * N + col;
            size_t o1 = (size_t)(row + 8) * N + col;
            if (res) {
                v0 += res[o0]; v1 += res[o0 + 1];
                v2 += res[o1]; v3 += res[o1 + 1];
            }
            if (half_out) {
                __half* Ch = (__half*)Cv;
                *(__half2*)&Ch[o0] = __floats2half2_rn(v0, v1);
                *(__half2*)&Ch[o1] = __floats2half2_rn(v2, v3);
            } else {
                float* C = (float*)Cv;
                C[o0] = v0; C[o0 + 1] = v1;
                C[o1] = v2; C[o1 + 1] = v3;
            }
        }
    }
}

// ---------------- fused flash attention v3: full fp16 MMA ----------------
#define QW 36
#define FLASH_SMEM ((128*QW + 2*64*QW + 2*64*QW + 2*64) * 4)

__global__ __launch_bounds__(256, 2)
void flash_kernel(const __half* __restrict__ qkv, const int* __restrict__ amask,
                  __half* __restrict__ ctx)
{
    extern __shared__ uint32_t fsm[];
    uint32_t* Qs = fsm;                      // [128][36]
    uint32_t* Ks = Qs + 128 * QW;            // [2][64][36]
    uint32_t* Vs = Ks + 2 * 64 * QW;         // [2][64][36]
    float* mk = (float*)(Vs + 2 * 64 * QW);  // [2][64]

    const int tid = threadIdx.x, w = tid >> 5, lane = tid & 31;
    const int g = lane >> 2, tig = lane & 3;
    const int bh = blockIdx.y, b = bh >> 4, h = bh & 15;
    const int row0 = (gridDim.x - 1 - blockIdx.x) * 128;   // heavy tiles first
    const int ntiles = row0 / 64 + 2;

    const __half* qb = qkv + (size_t)(b * SS + row0) * QKVS + h * 64;
    const __half* kb = qkv + (size_t)(b * SS) * QKVS + 1024 + h * 64;
    const __half* vb = qkv + (size_t)(b * SS) * QKVS + 2048 + h * 64;

    #pragma unroll
    for (int i = 0; i < 4; i++) {
        int c = tid + i * 256; int r = c >> 3, ch = c & 7;
        cpa16(&Qs[r * QW + ch * 4], qb + (size_t)r * QKVS + ch * 8);
    }
    #pragma unroll
    for (int i = 0; i < 2; i++) {
        int c = tid + i * 256; int r = c >> 3, ch = c & 7;
        cpa16(&Ks[r * QW + ch * 4], kb + (size_t)r * QKVS + ch * 8);
        cpa16(&Vs[r * QW + ch * 4], vb + (size_t)r * QKVS + ch * 8);
    }
    if (tid < 64) mk[tid] = amask[b * SS + tid] ? 0.f : -1e30f;
    cp_commit();

    float m0 = -1e30f, m1 = -1e30f, l0s = 0.f, l1s = 0.f;
    float acc_o[8][4];
    #pragma unroll
    for (int nt = 0; nt < 8; nt++)
        #pragma unroll
        for (int c = 0; c < 4; c++) acc_o[nt][c] = 0.f;

    const int mrow = w * 16 + g;
    const int grow0 = row0 + mrow, grow1 = grow0 + 8;
    const int vrow_off = (lane & 15) * QW + ((lane & 16) >> 2);

    for (int t = 0; t < ntiles; t++) {
        const int st = t & 1;
        cp_wait0();
        __syncthreads();
        if (t + 1 < ntiles) {
            int j0n = (t + 1) * 64, sn = st ^ 1;
            const __half* kn = kb + (size_t)j0n * QKVS;
            const __half* vn = vb + (size_t)j0n * QKVS;
            #pragma unroll
            for (int i = 0; i < 2; i++) {
                int c = tid + i * 256; int r = c >> 3, ch = c & 7;
                cpa16(&Ks[(sn * 64 + r) * QW + ch * 4], kn + (size_t)r * QKVS + ch * 8);
                cpa16(&Vs[(sn * 64 + r) * QW + ch * 4], vn + (size_t)r * QKVS + ch * 8);
            }
            if (tid < 64) mk[sn * 64 + tid] = amask[b * SS + j0n + tid] ? 0.f : -1e30f;
            cp_commit();
        }
        const int j0 = t * 64;
        const uint32_t* Ksb = Ks + st * 64 * QW;
        const uint32_t* Vsb = Vs + st * 64 * QW;
        const float* mkb = mk + st * 64;

        // ---- S = Q K^T ----
        float accs[8][4];
        #pragma unroll
        for (int nt = 0; nt < 8; nt++)
            #pragma unroll
            for (int c = 0; c < 4; c++) accs[nt][c] = 0.f;
        #pragma unroll
        for (int ks = 0; ks < 4; ks++) {
            uint32_t a0 = Qs[mrow * QW + ks * 8 + tig];
            uint32_t a1 = Qs[(mrow + 8) * QW + ks * 8 + tig];
            uint32_t a2 = Qs[mrow * QW + ks * 8 + tig + 4];
            uint32_t a3 = Qs[(mrow + 8) * QW + ks * 8 + tig + 4];
            #pragma unroll
            for (int nt = 0; nt < 8; nt++) {
                int n = g + nt * 8;
                uint32_t b0 = Ksb[n * QW + ks * 8 + tig];
                uint32_t b1 = Ksb[n * QW + ks * 8 + tig + 4];
                mma_f16(accs[nt], a0, a1, a2, a3, b0, b1);
            }
        }

        // ---- mask + scale + rowmax ----
        float rm0 = -1e30f, rm1 = -1e30f;
        #pragma unroll
        for (int nt = 0; nt < 8; nt++) {
            int c0 = j0 + nt * 8 + tig * 2;
            float ma = mkb[nt * 8 + tig * 2], mb = mkb[nt * 8 + tig * 2 + 1];
            float s0 = accs[nt][0] * 0.125f + ma;
            float s1 = accs[nt][1] * 0.125f + mb;
            float s2 = accs[nt][2] * 0.125f + ma;
            float s3 = accs[nt][3] * 0.125f + mb;
            if (c0 > grow0)     s0 = -1e30f;
            if (c0 + 1 > grow0) s1 = -1e30f;
            if (c0 > grow1)     s2 = -1e30f;
            if (c0 + 1 > grow1) s3 = -1e30f;
            accs[nt][0] = s0; accs[nt][1] = s1; accs[nt][2] = s2; accs[nt][3] = s3;
            rm0 = fmaxf(rm0, fmaxf(s0, s1));
            rm1 = fmaxf(rm1, fmaxf(s2, s3));
        }
        rm0 = fmaxf(rm0, __shfl_xor_sync(0xffffffffu, rm0, 1));
        rm0 = fmaxf(rm0, __shfl_xor_sync(0xffffffffu, rm0, 2));
        rm1 = fmaxf(rm1, __shfl_xor_sync(0xffffffffu, rm1, 1));
        rm1 = fmaxf(rm1, __shfl_xor_sync(0xffffffffu, rm1, 2));

        float mn0 = fmaxf(m0, rm0), mn1 = fmaxf(m1, rm1);
        float corr0 = __expf(m0 - mn0), corr1 = __expf(m1 - mn1);
        m0 = mn0; m1 = mn1;

        // ---- P = exp(S - m), row sums ----
        float sum0 = 0.f, sum1 = 0.f;
        #pragma unroll
        for (int nt = 0; nt < 8; nt++) {
            float p0 = __expf(accs[nt][0] - m0);
            float p1 = __expf(accs[nt][1] - m0);
            float p2 = __expf(accs[nt][2] - m1);
            float p3 = __expf(accs[nt][3] - m1);
            sum0 += p0 + p1; sum1 += p2 + p3;
            accs[nt][0] = p0; accs[nt][1] = p1; accs[nt][2] = p2; accs[nt][3] = p3;
        }
        sum0 += __shfl_xor_sync(0xffffffffu, sum0, 1);
        sum0 += __shfl_xor_sync(0xffffffffu, sum0, 2);
        sum1 += __shfl_xor_sync(0xffffffffu, sum1, 1);
        sum1 += __shfl_xor_sync(0xffffffffu, sum1, 2);
        l0s = l0s * corr0 + sum0;
        l1s = l1s * corr1 + sum1;
        #pragma unroll
        for (int nt = 0; nt < 8; nt++) {
            acc_o[nt][0] *= corr0; acc_o[nt][1] *= corr0;
            acc_o[nt][2] *= corr1; acc_o[nt][3] *= corr1;
        }

        // ---- O += P V ----
        #pragma unroll
        for (int ks = 0; ks < 4; ks++) {
            uint32_t a0 = pack_h2(accs[2 * ks][0],     accs[2 * ks][1]);
            uint32_t a1 = pack_h2(accs[2 * ks][2],     accs[2 * ks][3]);
            uint32_t a2 = pack_h2(accs[2 * ks + 1][0], accs[2 * ks + 1][1]);
            uint32_t a3 = pack_h2(accs[2 * ks + 1][2], accs[2 * ks + 1][3]);
            const uint32_t* vrow = Vsb + ks * 16 * QW + vrow_off;
            #pragma unroll
            for (int n0 = 0; n0 < 4; n0++) {
                uint32_t r0, r1, r2, r3;
                ldmx4t(r0, r1, r2, r3,
                       (uint32_t)__cvta_generic_to_shared(vrow + n0 * 8));
                mma_f16(acc_o[n0 * 2],     a0, a1, a2, a3, r0, r1);
                mma_f16(acc_o[n0 * 2 + 1], a0, a1, a2, a3, r2, r3);
            }
        }
    }

    float i0 = 1.f / l0s, i1 = 1.f / l1s;
    size_t base0 = (size_t)(b * SS + grow0) * DD + h * 64;
    size_t base1 = (size_t)(b * SS + grow1) * DD + h * 64;
    #pragma unroll
    for (int nt = 0; nt < 8; nt++) {
        int col = nt * 8 + tig * 2;
        *(__half2*)&ctx[base0 + col] = __floats2half2_rn(acc_o[nt][0] * i0,
                                                         acc_o[nt][1] * i0);
        *(__half2*)&ctx[base1 + col] = __floats2half2_rn(acc_o[nt][2] * i1,
                                                         acc_o[nt][3] * i1);
    }
}

// ---------------- host launch ----------------
extern "C" void kernel_launch(void* const* d_in, const int* in_sizes, int n_in,
                              void* d_out, int out_size)
{
    const float* x     = (const float*)d_in[0];
    const int*   amask = (const int*)  d_in[1];
    const float* wq    = (const float*)d_in[2];
    const float* wk    = (const float*)d_in[3];
    const float* wv    = (const float*)d_in[4];
    const float* wo    = (const float*)d_in[5];
    const float* bo    = (const float*)d_in[6];
    const float* ln1s  = (const float*)d_in[7];
    const float* ln1b  = (const float*)d_in[8];
    const float* ln2s  = (const float*)d_in[9];
    const float* ln2b  = (const float*)d_in[10];
    const float* w1    = (const float*)d_in[11];
    const float* b1    = (const float*)d_in[12];
    const float* w2    = (const float*)d_in[13];
    const float* b2    = (const float*)d_in[14];
    float* out = (float*)d_out;

    __half *hh, *qkvh, *ctxh, *h2h, *midh;
    float *x2;
    uint32_t* wp;
    cudaGetSymbolAddress((void**)&hh,   g_hh);
    cudaGetSymbolAddress((void**)&qkvh, g_qkvh);
    cudaGetSymbolAddress((void**)&ctxh, g_ctxh);
    cudaGetSymbolAddress((void**)&x2,   g_x2);
    cudaGetSymbolAddress((void**)&h2h,  g_h2h);
    cudaGetSymbolAddress((void**)&midh, g_midh);
    cudaGetSymbolAddress((void**)&wp,   g_wp);

    uint32_t* wqkvP = wp;                                   // [512][3072]
    uint32_t* woP   = wp + 512 * 3072;                      // [512][1024]
    uint32_t* w1P   = woP + 512 * 1024;                     // [512][4096]
    uint32_t* w2P   = w1P + 512 * 4096;                     // [2048][1024]

    cudaFuncSetAttribute(flash_kernel,
                         cudaFuncAttributeMaxDynamicSharedMemorySize, FLASH_SMEM);
    cudaFuncSetAttribute(gemm_f16,
                         cudaFuncAttributeMaxDynamicSharedMemorySize, GSMEM);

    // weight packing (fp32 -> half2 k-pair packed)
    pack_qkvh<<<2048, 256>>>(wq, wk, wv, wqkvP);
    pack_wh<<<2048, 256>>>(wo, woP, 1024);
    pack_wh<<<8192, 256>>>(w1, w1P, 4096);
    pack_wh<<<8192, 256>>>(w2, w2P, 1024);

    // LN1 (fp16 output)
    ln_kernel<<<BS, 256>>>(x, ln1s, ln1b, hh);

    // fused QKV projection -> fp16 qkv
    gemm_f16<<<dim3(QKVS / 128, BS / 128), 128, GSMEM>>>(
        hh, wqkvP, qkvh, BS, QKVS, DD, nullptr, nullptr, 0, 1);

    // fused attention (full fp16) -> fp16 ctx
    flash_kernel<<<dim3(SS / 128, BB * HH), 256, FLASH_SMEM>>>(qkvh, amask, ctxh);

    // output projection + residual -> fp32 x2
    gemm_f16<<<dim3(DD / 128, BS / 128), 128, GSMEM>>>(
        ctxh, woP, x2, BS, DD, DD, bo, x, 0, 0);

    // LN2 + FFN
    ln_kernel<<<BS, 256>>>(x2, ln2s, ln2b, h2h);
    gemm_f16<<<dim3(DFF / 128, BS / 128), 128, GSMEM>>>(
        h2h, w1P, midh, BS, DFF, DD, b1, nullptr, 1, 1);
    gemm_f16<<<dim3(DD / 128, BS / 128), 128, GSMEM>>>(
        midh, w2P, out, BS, DD, DFF, b2, x2, 0, 0);
}

// round 17
// speedup vs baseline: 1.3080x; 1.0719x over previous
#include <cuda_runtime.h>
#include <cuda_fp16.h>
#include <math.h>
#include <stdint.h>

#define BB 4
#define SS 1024
#define DD 1024
#define HH 16
#define HD 64
#define BS (BB*SS)     /* 4096 */
#define DFF (4*DD)     /* 4096 */
#define QKVS 3072

// ---------------- scratch (static __device__, no allocations) ----------------
__device__ __half g_hh  [BS*DD];
__device__ __half g_qkvh[BS*QKVS];
__device__ __half g_ctxh[BS*DD];
__device__ float  g_x2  [BS*DD];
__device__ __half g_h2h [BS*DD];
__device__ __half g_midh[BS*DFF];
// packed half2 weights: wqkv [512][3072], wo [512][1024], w1 [512][4096], w2 [2048][1024]
__device__ uint32_t g_wp[512*3072 + 512*1024 + 512*4096 + 2048*1024];

// ---------------- helpers ----------------
__device__ __forceinline__ void cpa16(void* d, const void* s) {
    asm volatile("cp.async.cg.shared.global [%0], [%1], 16;\n"
                 :: "r"((uint32_t)__cvta_generic_to_shared(d)), "l"(s));
}
__device__ __forceinline__ void cp_commit() { asm volatile("cp.async.commit_group;\n"); }
__device__ __forceinline__ void cp_wait0()  { asm volatile("cp.async.wait_group 0;\n"); }
__device__ __forceinline__ void cp_wait1()  { asm volatile("cp.async.wait_group 1;\n"); }

__device__ __forceinline__ uint32_t pack_h2(float x, float y) {
    __half2 h = __floats2half2_rn(x, y);
    return *(uint32_t*)&h;
}

__device__ __forceinline__ float gelu_f(float x) {
    float t = 0.7978845608028654f * (x + 0.044715f * x * x * x);
    return 0.5f * x * (1.0f + tanhf(t));
}

// fp16 m16n8k16 MMA, fp32 accumulate
__device__ __forceinline__ void mma_f16(float* c, uint32_t a0, uint32_t a1,
                                        uint32_t a2, uint32_t a3,
                                        uint32_t b0, uint32_t b1) {
    asm volatile(
        "mma.sync.aligned.m16n8k16.row.col.f32.f16.f16.f32 "
        "{%0,%1,%2,%3}, {%4,%5,%6,%7}, {%8,%9}, {%0,%1,%2,%3};"
        : "+f"(c[0]), "+f"(c[1]), "+f"(c[2]), "+f"(c[3])
        : "r"(a0), "r"(a1), "r"(a2), "r"(a3), "r"(b0), "r"(b1));
}

__device__ __forceinline__ void ldmx4t(uint32_t& r0, uint32_t& r1,
                                       uint32_t& r2, uint32_t& r3, uint32_t addr) {
    asm volatile("ldmatrix.sync.aligned.m8n8.x4.trans.shared.b16 "
                 "{%0,%1,%2,%3}, [%4];"
                 : "=r"(r0), "=r"(r1), "=r"(r2), "=r"(r3) : "r"(addr));
}

// ---------------- fused weight packing: all four regions in one launch --------
// Region A (blocks [0,2048)):      wq/wk/wv -> wqkvP [512][3072]
// Region B (blocks [2048,4096)):   wo -> woP [512][1024]
// Region C (blocks [4096,12288)):  w1 -> w1P [512][4096]
// Region D (blocks [12288,20480)): w2 -> w2P [2048][1024]
__global__ void pack_all(const float* __restrict__ wq, const float* __restrict__ wk,
                         const float* __restrict__ wv, const float* __restrict__ wo,
                         const float* __restrict__ w1, const float* __restrict__ w2,
                         uint32_t* __restrict__ wp)
{
    int blk = blockIdx.x;
    if (blk < 2048) {
        int idx = blk * 256 + threadIdx.x;          // over 512*1024
        int kc = idx >> 10, n = idx & 1023;
        size_t i0 = (size_t)(2 * kc) * 1024 + n;
        size_t i1 = i0 + 1024;
        size_t o = (size_t)kc * QKVS + n;
        uint32_t* out = wp;
        out[o]        = pack_h2(wq[i0], wq[i1]);
        out[o + 1024] = pack_h2(wk[i0], wk[i1]);
        out[o + 2048] = pack_h2(wv[i0], wv[i1]);
    } else if (blk < 4096) {
        int idx = (blk - 2048) * 256 + threadIdx.x; // over 512*1024, N=1024
        int kc = idx >> 10, n = idx & 1023;
        size_t i0 = (size_t)(2 * kc) * 1024 + n;
        wp[512 * 3072 + idx] = pack_h2(wo[i0], wo[i0 + 1024]);
    } else if (blk < 12288) {
        int idx = (blk - 4096) * 256 + threadIdx.x; // over 512*4096, N=4096
        int kc = idx >> 12, n = idx & 4095;
        size_t i0 = (size_t)(2 * kc) * 4096 + n;
        wp[512 * 3072 + 512 * 1024 + idx] = pack_h2(w1[i0], w1[i0 + 4096]);
    } else {
        int idx = (blk - 12288) * 256 + threadIdx.x; // over 2048*1024, N=1024
        int kc = idx >> 10, n = idx & 1023;
        size_t i0 = (size_t)(2 * kc) * 1024 + n;
        wp[512 * 3072 + 512 * 1024 + 512 * 4096 + idx] = pack_h2(w2[i0], w2[i0 + 1024]);
    }
}

// ---------------- layernorm: fp32 in, fp16 out ----------------
__global__ void ln_kernel(const float* __restrict__ x,
                          const float* __restrict__ scale,
                          const float* __restrict__ shift,
                          __half* __restrict__ out)
{
    int row = blockIdx.x;
    int t = threadIdx.x;
    const float4 xv = ((const float4*)(x + (size_t)row * DD))[t];
    __shared__ float red[256];

    float s = xv.x + xv.y + xv.z + xv.w;
    red[t] = s; __syncthreads();
    for (int o = 128; o > 0; o >>= 1) { if (t < o) red[t] += red[t + o]; __syncthreads(); }
    float mean = red[0] * (1.0f / DD);
    __syncthreads();

    float d0 = xv.x - mean, d1 = xv.y - mean, d2 = xv.z - mean, d3 = xv.w - mean;
    red[t] = d0 * d0 + d1 * d1 + d2 * d2 + d3 * d3; __syncthreads();
    for (int o = 128; o > 0; o >>= 1) { if (t < o) red[t] += red[t + o]; __syncthreads(); }
    float rstd = rsqrtf(red[0] * (1.0f / DD) + 1e-5f);

    float4 sc = ((const float4*)scale)[t];
    float4 sh = ((const float4*)shift)[t];
    __half2* orow = (__half2*)(out + (size_t)row * DD);
    orow[t * 2]     = __floats2half2_rn(sc.x * d0 * rstd + sh.x, sc.y * d1 * rstd + sh.y);
    orow[t * 2 + 1] = __floats2half2_rn(sc.z * d2 * rstd + sh.z, sc.w * d3 * rstd + sh.w);
}

// ---------------- fp16 GEMM (R14): 128 thr, 128x128 CTA, k16 stages, 3-stage ----
#define ASZ (128*12)
#define BSZ (8*136)
#define STG (ASZ+BSZ)
#define GSMEM (3*STG*4)

__global__ __launch_bounds__(128)
void gemm_f16(const __half* __restrict__ A, const uint32_t* __restrict__ Bp,
              void* __restrict__ Cv, int M, int N, int K,
              const float* __restrict__ bias,
              const float* __restrict__ res,
              int gelu, int half_out)
{
    extern __shared__ uint32_t smh[];
    const int tid  = threadIdx.x;
    const int lane = tid & 31;
    const int warp = tid >> 5;           // 0..3
    const int g    = lane >> 2;
    const int tig  = lane & 3;
    const int mw   = (warp >> 1) * 64;   // 0 or 64
    const int nw   = (warp & 1) * 64;    // 0 or 64
    const int bx = blockIdx.x, by = blockIdx.y;

    const __half* Ab = A + (size_t)(by * 128) * K;
    const uint32_t* Bb = Bp + bx * 128;

    float acc[4][8][4];
    #pragma unroll
    for (int i = 0; i < 4; i++)
        #pragma unroll
        for (int j = 0; j < 8; j++)
            #pragma unroll
            for (int c = 0; c < 4; c++) acc[i][j][c] = 0.f;

    const int T = K / 16;
    const int ar = tid >> 1, ak = tid & 1;
    const int br = tid >> 5, bn = (tid & 31) * 4;

#define ISSUE(sidx, k0) do {                                                     \
        uint32_t* As_ = smh + (sidx) * STG;                                      \
        uint32_t* Bs_ = As_ + ASZ;                                               \
        cpa16(&As_[ar * 12 + ak * 4],        Ab + (size_t)ar * K + (k0) + ak * 8); \
        cpa16(&As_[(ar + 64) * 12 + ak * 4], Ab + (size_t)(ar + 64) * K + (k0) + ak * 8); \
        cpa16(&Bs_[br * 136 + bn],       Bb + (size_t)(((k0) >> 1) + br) * N + bn); \
        cpa16(&Bs_[(br + 4) * 136 + bn], Bb + (size_t)(((k0) >> 1) + br + 4) * N + bn); \
        cp_commit();                                                             \
    } while (0)

    ISSUE(0, 0);
    ISSUE(1, 16);

    int st = 0;
    for (int t = 0; t < T; t++) {
        if (t + 2 < T) cp_wait1(); else cp_wait0();
        __syncthreads();
        if (t + 2 < T) {
            int sn = st + 2; if (sn >= 3) sn -= 3;
            ISSUE(sn, (t + 2) * 16);
        }
        const uint32_t* As = smh + st * STG;
        const uint32_t* Bs = As + ASZ;
        {
            uint32_t a[4][4], b[8][2];
            #pragma unroll
            for (int i = 0; i < 4; i++) {
                int m = mw + i * 16 + g;
                a[i][0] = As[m * 12 + tig];
                a[i][1] = As[(m + 8) * 12 + tig];
                a[i][2] = As[m * 12 + tig + 4];
                a[i][3] = As[(m + 8) * 12 + tig + 4];
            }
            #pragma unroll
            for (int j = 0; j < 8; j++) {
                int n = nw + j * 8 + g;
                b[j][0] = Bs[tig * 136 + n];
                b[j][1] = Bs[(tig + 4) * 136 + n];
            }
            #pragma unroll
            for (int i = 0; i < 4; i++)
                #pragma unroll
                for (int j = 0; j < 8; j++)
                    mma_f16(acc[i][j], a[i][0], a[i][1], a[i][2], a[i][3],
                            b[j][0], b[j][1]);
        }
        st++; if (st >= 3) st -= 3;
    }
#undef ISSUE

    #pragma unroll
    for (int i = 0; i < 4; i++) {
        int row = by * 128 + mw + i * 16 + g;
        #pragma unroll
        for (int j = 0; j < 8; j++) {
            int col = bx * 128 + nw + j * 8 + tig * 2;
            float v0 = acc[i][j][0], v1 = acc[i][j][1];
            float v2 = acc[i][j][2], v3 = acc[i][j][3];
            if (bias) {
                float b0 = bias[col], b1 = bias[col + 1];
                v0 += b0; v1 += b1; v2 += b0; v3 += b1;
            }
            if (gelu) { v0 = gelu_f(v0); v1 = gelu_f(v1); v2 = gelu_f(v2); v3 = gelu_f(v3); }
            size_t o0 = (size_t)row * N + col;
            size_t o1 = (size_t)(row + 8) * N + col;
            if (res) {
                v0 += res[o0]; v1 += res[o0 + 1];
                v2 += res[o1]; v3 += res[o1 + 1];
            }
            if (half_out) {
                __half* Ch = (__half*)Cv;
                *(__half2*)&Ch[o0] = __floats2half2_rn(v0, v1);
                *(__half2*)&Ch[o1] = __floats2half2_rn(v2, v3);
            } else {
                float* C = (float*)Cv;
                C[o0] = v0; C[o0 + 1] = v1;
                C[o1] = v2; C[o1 + 1] = v3;
            }
        }
    }
}

// ---------------- fused flash attention v3: full fp16 MMA (R14) ----------------
#define QW 36
#define FLASH_SMEM ((128*QW + 2*64*QW + 2*64*QW + 2*64) * 4)

__global__ __launch_bounds__(256, 2)
void flash_kernel(const __half* __restrict__ qkv, const int* __restrict__ amask,
                  __half* __restrict__ ctx)
{
    extern __shared__ uint32_t fsm[];
    uint32_t* Qs = fsm;                      // [128][36]
    uint32_t* Ks = Qs + 128 * QW;            // [2][64][36]
    uint32_t* Vs = Ks + 2 * 64 * QW;         // [2][64][36]
    float* mk = (float*)(Vs + 2 * 64 * QW);  // [2][64]

    const int tid = threadIdx.x, w = tid >> 5, lane = tid & 31;
    const int g = lane >> 2, tig = lane & 3;
    const int bh = blockIdx.y, b = bh >> 4, h = bh & 15;
    const int row0 = (gridDim.x - 1 - blockIdx.x) * 128;   // heavy tiles first
    const int ntiles = row0 / 64 + 2;

    const __half* qb = qkv + (size_t)(b * SS + row0) * QKVS + h * 64;
    const __half* kb = qkv + (size_t)(b * SS) * QKVS + 1024 + h * 64;
    const __half* vb = qkv + (size_t)(b * SS) * QKVS + 2048 + h * 64;

    #pragma unroll
    for (int i = 0; i < 4; i++) {
        int c = tid + i * 256; int r = c >> 3, ch = c & 7;
        cpa16(&Qs[r * QW + ch * 4], qb + (size_t)r * QKVS + ch * 8);
    }
    #pragma unroll
    for (int i = 0; i < 2; i++) {
        int c = tid + i * 256; int r = c >> 3, ch = c & 7;
        cpa16(&Ks[r * QW + ch * 4], kb + (size_t)r * QKVS + ch * 8);
        cpa16(&Vs[r * QW + ch * 4], vb + (size_t)r * QKVS + ch * 8);
    }
    if (tid < 64) mk[tid] = amask[b * SS + tid] ? 0.f : -1e30f;
    cp_commit();

    float m0 = -1e30f, m1 = -1e30f, l0s = 0.f, l1s = 0.f;
    float acc_o[8][4];
    #pragma unroll
    for (int nt = 0; nt < 8; nt++)
        #pragma unroll
        for (int c = 0; c < 4; c++) acc_o[nt][c] = 0.f;

    const int mrow = w * 16 + g;
    const int grow0 = row0 + mrow, grow1 = grow0 + 8;
    const int vrow_off = (lane & 15) * QW + ((lane & 16) >> 2);

    for (int t = 0; t < ntiles; t++) {
        const int st = t & 1;
        cp_wait0();
        __syncthreads();
        if (t + 1 < ntiles) {
            int j0n = (t + 1) * 64, sn = st ^ 1;
            const __half* kn = kb + (size_t)j0n * QKVS;
            const __half* vn = vb + (size_t)j0n * QKVS;
            #pragma unroll
            for (int i = 0; i < 2; i++) {
                int c = tid + i * 256; int r = c >> 3, ch = c & 7;
                cpa16(&Ks[(sn * 64 + r) * QW + ch * 4], kn + (size_t)r * QKVS + ch * 8);
                cpa16(&Vs[(sn * 64 + r) * QW + ch * 4], vn + (size_t)r * QKVS + ch * 8);
            }
            if (tid < 64) mk[sn * 64 + tid] = amask[b * SS + j0n + tid] ? 0.f : -1e30f;
            cp_commit();
        }
        const int j0 = t * 64;
        const uint32_t* Ksb = Ks + st * 64 * QW;
        const uint32_t* Vsb = Vs + st * 64 * QW;
        const float* mkb = mk + st * 64;

        // ---- S = Q K^T ----
        float accs[8][4];
        #pragma unroll
        for (int nt = 0; nt < 8; nt++)
            #pragma unroll
            for (int c = 0; c < 4; c++) accs[nt][c] = 0.f;
        #pragma unroll
        for (int ks = 0; ks < 4; ks++) {
            uint32_t a0 = Qs[mrow * QW + ks * 8 + tig];
            uint32_t a1 = Qs[(mrow + 8) * QW + ks * 8 + tig];
            uint32_t a2 = Qs[mrow * QW + ks * 8 + tig + 4];
            uint32_t a3 = Qs[(mrow + 8) * QW + ks * 8 + tig + 4];
            #pragma unroll
            for (int nt = 0; nt < 8; nt++) {
                int n = g + nt * 8;
                uint32_t b0 = Ksb[n * QW + ks * 8 + tig];
                uint32_t b1 = Ksb[n * QW + ks * 8 + tig + 4];
                mma_f16(accs[nt], a0, a1, a2, a3, b0, b1);
            }
        }

        // ---- mask + scale + rowmax ----
        float rm0 = -1e30f, rm1 = -1e30f;
        #pragma unroll
        for (int nt = 0; nt < 8; nt++) {
            int c0 = j0 + nt * 8 + tig * 2;
            float ma = mkb[nt * 8 + tig * 2], mb = mkb[nt * 8 + tig * 2 + 1];
            float s0 = accs[nt][0] * 0.125f + ma;
            float s1 = accs[nt][1] * 0.125f + mb;
            float s2 = accs[nt][2] * 0.125f + ma;
            float s3 = accs[nt][3] * 0.125f + mb;
            if (c0 > grow0)     s0 = -1e30f;
            if (c0 + 1 > grow0) s1 = -1e30f;
            if (c0 > grow1)     s2 = -1e30f;
            if (c0 + 1 > grow1) s3 = -1e30f;
            accs[nt][0] = s0; accs[nt][1] = s1; accs[nt][2] = s2; accs[nt][3] = s3;
            rm0 = fmaxf(rm0, fmaxf(s0, s1));
            rm1 = fmaxf(rm1, fmaxf(s2, s3));
        }
        rm0 = fmaxf(rm0, __shfl_xor_sync(0xffffffffu, rm0, 1));
        rm0 = fmaxf(rm0, __shfl_xor_sync(0xffffffffu, rm0, 2));
        rm1 = fmaxf(rm1, __shfl_xor_sync(0xffffffffu, rm1, 1));
        rm1 = fmaxf(rm1, __shfl_xor_sync(0xffffffffu, rm1, 2));

        float mn0 = fmaxf(m0, rm0), mn1 = fmaxf(m1, rm1);
        float corr0 = __expf(m0 - mn0), corr1 = __expf(m1 - mn1);
        m0 = mn0; m1 = mn1;

        // ---- P = exp(S - m), row sums ----
        float sum0 = 0.f, sum1 = 0.f;
        #pragma unroll
        for (int nt = 0; nt < 8; nt++) {
            float p0 = __expf(accs[nt][0] - m0);
            float p1 = __expf(accs[nt][1] - m0);
            float p2 = __expf(accs[nt][2] - m1);
            float p3 = __expf(accs[nt][3] - m1);
            sum0 += p0 + p1; sum1 += p2 + p3;
            accs[nt][0] = p0; accs[nt][1] = p1; accs[nt][2] = p2; accs[nt][3] = p3;
        }
        sum0 += __shfl_xor_sync(0xffffffffu, sum0, 1);
        sum0 += __shfl_xor_sync(0xffffffffu, sum0, 2);
        sum1 += __shfl_xor_sync(0xffffffffu, sum1, 1);
        sum1 += __shfl_xor_sync(0xffffffffu, sum1, 2);
        l0s = l0s * corr0 + sum0;
        l1s = l1s * corr1 + sum1;
        #pragma unroll
        for (int nt = 0; nt < 8; nt++) {
            acc_o[nt][0] *= corr0; acc_o[nt][1] *= corr0;
            acc_o[nt][2] *= corr1; acc_o[nt][3] *= corr1;
        }

        // ---- O += P V ----
        #pragma unroll
        for (int ks = 0; ks < 4; ks++) {
            uint32_t a0 = pack_h2(accs[2 * ks][0],     accs[2 * ks][1]);
            uint32_t a1 = pack_h2(accs[2 * ks][2],     accs[2 * ks][3]);
            uint32_t a2 = pack_h2(accs[2 * ks + 1][0], accs[2 * ks + 1][1]);
            uint32_t a3 = pack_h2(accs[2 * ks + 1][2], accs[2 * ks + 1][3]);
            const uint32_t* vrow = Vsb + ks * 16 * QW + vrow_off;
            #pragma unroll
            for (int n0 = 0; n0 < 4; n0++) {
                uint32_t r0, r1, r2, r3;
                ldmx4t(r0, r1, r2, r3,
                       (uint32_t)__cvta_generic_to_shared(vrow + n0 * 8));
                mma_f16(acc_o[n0 * 2],     a0, a1, a2, a3, r0, r1);
                mma_f16(acc_o[n0 * 2 + 1], a0, a1, a2, a3, r2, r3);
            }
        }
    }

    float i0 = 1.f / l0s, i1 = 1.f / l1s;
    size_t base0 = (size_t)(b * SS + grow0) * DD + h * 64;
    size_t base1 = (size_t)(b * SS + grow1) * DD + h * 64;
    #pragma unroll
    for (int nt = 0; nt < 8; nt++) {
        int col = nt * 8 + tig * 2;
        *(__half2*)&ctx[base0 + col] = __floats2half2_rn(acc_o[nt][0] * i0,
                                                         acc_o[nt][1] * i0);
        *(__half2*)&ctx[base1 + col] = __floats2half2_rn(acc_o[nt][2] * i1,
                                                         acc_o[nt][3] * i1);
    }
}

// ---------------- host launch ----------------
extern "C" void kernel_launch(void* const* d_in, const int* in_sizes, int n_in,
                              void* d_out, int out_size)
{
    const float* x     = (const float*)d_in[0];
    const int*   amask = (const int*)  d_in[1];
    const float* wq    = (const float*)d_in[2];
    const float* wk    = (const float*)d_in[3];
    const float* wv    = (const float*)d_in[4];
    const float* wo    = (const float*)d_in[5];
    const float* bo    = (const float*)d_in[6];
    const float* ln1s  = (const float*)d_in[7];
    const float* ln1b  = (const float*)d_in[8];
    const float* ln2s  = (const float*)d_in[9];
    const float* ln2b  = (const float*)d_in[10];
    const float* w1    = (const float*)d_in[11];
    const float* b1    = (const float*)d_in[12];
    const float* w2    = (const float*)d_in[13];
    const float* b2    = (const float*)d_in[14];
    float* out = (float*)d_out;

    __half *hh, *qkvh, *ctxh, *h2h, *midh;
    float *x2;
    uint32_t* wp;
    cudaGetSymbolAddress((void**)&hh,   g_hh);
    cudaGetSymbolAddress((void**)&qkvh, g_qkvh);
    cudaGetSymbolAddress((void**)&ctxh, g_ctxh);
    cudaGetSymbolAddress((void**)&x2,   g_x2);
    cudaGetSymbolAddress((void**)&h2h,  g_h2h);
    cudaGetSymbolAddress((void**)&midh, g_midh);
    cudaGetSymbolAddress((void**)&wp,   g_wp);

    uint32_t* wqkvP = wp;                                   // [512][3072]
    uint32_t* woP   = wp + 512 * 3072;                      // [512][1024]
    uint32_t* w1P   = woP + 512 * 1024;                     // [512][4096]
    uint32_t* w2P   = w1P + 512 * 4096;                     // [2048][1024]

    cudaFuncSetAttribute(flash_kernel,
                         cudaFuncAttributeMaxDynamicSharedMemorySize, FLASH_SMEM);
    cudaFuncSetAttribute(gemm_f16,
                         cudaFuncAttributeMaxDynamicSharedMemorySize, GSMEM);

    // fused weight packing (all regions concurrent)
    pack_all<<<20480, 256>>>(wq, wk, wv, wo, w1, w2, wp);

    // LN1 (fp16 output)
    ln_kernel<<<BS, 256>>>(x, ln1s, ln1b, hh);

    // fused QKV projection -> fp16 qkv
    gemm_f16<<<dim3(QKVS / 128, BS / 128), 128, GSMEM>>>(
        hh, wqkvP, qkvh, BS, QKVS, DD, nullptr, nullptr, 0, 1);

    // fused attention (full fp16) -> fp16 ctx
    flash_kernel<<<dim3(SS / 128, BB * HH), 256, FLASH_SMEM>>>(qkvh, amask, ctxh);

    // output projection + residual -> fp32 x2
    gemm_f16<<<dim3(DD / 128, BS / 128), 128, GSMEM>>>(
        ctxh, woP, x2, BS, DD, DD, bo, x, 0, 0);

    // LN2 + FFN
    ln_kernel<<<BS, 256>>>(x2, ln2s, ln2b, h2h);
    gemm_f16<<<dim3(DFF / 128, BS / 128), 128, GSMEM>>>(
        h2h, w1P, midh, BS, DFF, DD, b1, nullptr, 1, 1);
    gemm_f16<<<dim3(DD / 128, BS / 128), 128, GSMEM>>>(
        midh, w2P, out, BS, DD, DFF, b2, x2, 0, 0);
}